// round 15
// baseline (speedup 1.0000x reference)
#include <cuda_runtime.h>
#include <math.h>

#define Bc   32
#define Tc   256
#define Fc   32
#define HIDc 128
#define ZW   640
#define Vc   101
#define LBLc 32
#define NEGF (-1e30f)

#define NCTA 128
#define NTHR 256
#define WSTRIDE 2564                 // per-cg weight stride in floats (16B-aligned)
#define HSTRIDE 258                  // per-row dup-h stride (8B-aligned, conflict-free)
#define SW_FLOATS (8*WSTRIDE)
#define SH_FLOATS (72*HSTRIDE)
#define SC_FLOATS (2*8*64*2)
#define SMEM_BYTES ((SW_FLOATS+SH_FLOATS+SC_FLOATS)*4)

// ---------------------------------------------------------------------------
// Device scratch.
// ---------------------------------------------------------------------------
__device__ __align__(16) float g_h[2][Fc][Bc][HIDc];
__device__ __align__(16) float g_c[2][Fc][Bc][HIDc];
__device__ __align__(16) float g_feat[Bc][Tc][HIDc];
__device__ __align__(16) float g_logp[Bc][Tc][Vc];
__device__ unsigned g_cnt4[4 * 32];
__device__ unsigned g_gen4[4 * 32];

__device__ __forceinline__ float fsig(float x) {
    return __fdividef(1.0f, 1.0f + __expf(-x));
}
__device__ __forceinline__ float ftanh(float x) {
    return 1.0f - __fdividef(2.0f, __expf(2.0f * x) + 1.0f);
}

__device__ __forceinline__ unsigned long long pack2f(float lo, float hi) {
    unsigned long long r;
    asm("mov.b64 %0, {%1, %2};" : "=l"(r) : "f"(lo), "f"(hi));
    return r;
}
__device__ __forceinline__ void unpack2f(unsigned long long v, float& lo, float& hi) {
    asm("mov.b64 {%0, %1}, %2;" : "=f"(lo), "=f"(hi) : "l"(v));
}
__device__ __forceinline__ unsigned long long fma2(unsigned long long a,
                                                   unsigned long long b,
                                                   unsigned long long c) {
    unsigned long long d;
    asm("fma.rn.f32x2 %0, %1, %2, %3;" : "=l"(d) : "l"(a), "l"(b), "l"(c));
    return d;
}

__global__ void init_kernel() {
    const int nh = 2 * Fc * Bc * HIDc;
    float* ph = &g_h[0][0][0][0];
    float* pc = &g_c[0][0][0][0];
    for (int i = blockIdx.x * blockDim.x + threadIdx.x; i < nh;
         i += gridDim.x * blockDim.x) { ph[i] = 0.0f; pc[i] = 0.0f; }
    const int nf = Bc * Tc * HIDc;
    float* pf = &g_feat[0][0][0];
    for (int i = blockIdx.x * blockDim.x + threadIdx.x; i < nf;
         i += gridDim.x * blockDim.x) pf[i] = 0.0f;
    if (blockIdx.x == 0 && threadIdx.x < 4 * 32) {
        g_cnt4[threadIdx.x] = 0u;
        g_gen4[threadIdx.x] = 0u;
    }
}

// Split per-bg grid barrier (32 CTAs).
__device__ __forceinline__ void gbar_arrive(int bg) {
    __syncthreads();
    if (threadIdx.x == 0) {
        unsigned old;
        asm volatile("atom.acq_rel.gpu.global.add.u32 %0, [%1], %2;"
                     : "=r"(old) : "l"(&g_cnt4[bg * 32]), "r"(1u) : "memory");
        unsigned done = old + 1u;
        if ((done & 31u) == 0u) {
            asm volatile("st.release.gpu.global.u32 [%0], %1;"
                         :: "l"(&g_gen4[bg * 32]), "r"(done >> 5) : "memory");
        }
    }
}
__device__ __forceinline__ void gbar_wait(unsigned target, int bg) {
    const unsigned* gen = &g_gen4[bg * 32];
    unsigned cur;
    do {
        asm volatile("ld.acquire.gpu.global.u32 %0, [%1];"
                     : "=r"(cur) : "l"(gen) : "memory");
    } while (cur < target);
}

// ---------------------------------------------------------------------------
// Persistent MDLSTM wavefront (R14, unchanged — proven at 4172us).
// ---------------------------------------------------------------------------
__global__ __launch_bounds__(NTHR, 1)
void mdlstm_persist(const float* __restrict__ X,
                    const float* __restrict__ Wx,
                    const float* __restrict__ Wh1,
                    const float* __restrict__ Wh2,
                    const float* __restrict__ bias)
{
    extern __shared__ float smem[];
    float* s_w  = smem;
    float* s_h2 = smem + SW_FLOATS;
    float* s_c  = smem + SW_FLOATS + SH_FLOATS;

    const int tid  = threadIdx.x;
    const int bx   = blockIdx.x;
    const int jkb  = bx & 7;
    const int bg   = (bx >> 3) & 3;
    const int cgid = bx >> 5;

    const int half = tid >> 7;
    const int cg   = (tid >> 4) & 7;
    const int rg   = tid & 15;

    for (int i = tid; i < 8 * 5 * 256 * 2; i += NTHR) {
        int c   = i & 1;
        int k   = (i >> 1) & 255;
        int t2  = i >> 9;
        int g   = t2 % 5;
        int cgl = t2 / 5;
        int col = g * HIDc + jkb * 16 + cgl * 2 + c;
        float v = (k < 128) ? Wh1[k * ZW + col] : Wh2[(k - 128) * ZW + col];
        s_w[cgl * WSTRIDE + ((g << 8) + k) * 2 + c] = v;
    }

    const int kk0 = jkb * 16 + cg * 2;
    float wxl[5], wxh[5], bl0[5], bl1[5];
#pragma unroll
    for (int g = 0; g < 5; g++) {
        int col = g * HIDc + kk0;
        wxl[g] = Wx[col];  wxh[g] = Wx[col + 1];
        bl0[g] = bias[col]; bl1[g] = bias[col + 1];
    }

    int rowj[2], cellj[2], bbj[2];
    rowj[0] = rg + 32 * half;
    rowj[1] = rowj[0] + 16;
#pragma unroll
    for (int j = 0; j < 2; j++) {
        cellj[j] = cgid * 8 + (rowj[j] >> 3);
        bbj[j]   = bg * 8 + (rowj[j] & 7);
    }

    const float* wp  = s_w + cg * WSTRIDE;
    const float* up0 = s_h2 + rowj[0] * HSTRIDE;
    const float* up1 = s_h2 + rowj[1] * HSTRIDE;
    const float* lf0 = up0 + 8 * HSTRIDE;
    const float* lf1 = up1 + 8 * HSTRIDE;

    float2 c_reg[2] = {make_float2(0.f, 0.f), make_float2(0.f, 0.f)};

    __syncthreads();

    for (int d = 0; d < Tc + Fc - 1; d++) {
        const int h_lo = (d > Tc - 1) ? d - (Tc - 1) : 0;
        const int h_hi = (d < Fc - 1) ? d : (Fc - 1);
        const int ncells = h_hi - h_lo + 1;
        const int rd = (d + 1) & 1, wr = d & 1;
        const bool regB = (d > Tc - 1);

        bool val[2]; int hh[2], ww[2];
#pragma unroll
        for (int j = 0; j < 2; j++) {
            val[j] = cellj[j] < ncells;
            hh[j]  = h_lo + cellj[j];
            ww[j]  = d - hh[j];
        }

        // Peer-independent work before the barrier wait.
        float xv[2];
#pragma unroll
        for (int j = 0; j < 2; j++)
            xv[j] = val[j] ? __ldg(&X[bbj[j] * (Tc * Fc) + ww[j] * Fc + hh[j]]) : 0.f;

        unsigned long long acc[2][5];
#pragma unroll
        for (int j = 0; j < 2; j++)
#pragma unroll
            for (int g = 0; g < 5; g++)
                acc[j][g] = pack2f(fmaf(xv[j], wxl[g], bl0[g]),
                                   fmaf(xv[j], wxh[g], bl1[g]));

        if (d > 0) gbar_wait((unsigned)d, bg);

        float2 cbnd = make_float2(0.f, 0.f);
        if (!regB) {
            if (rowj[0] < 8 && val[0] && hh[0] > 0)
                cbnd = __ldcg((const float2*)&g_c[rd][hh[0] - 1][bbj[0]][kk0]);
        } else {
            if (rowj[1] >= 56 && val[1])
                cbnd = __ldcg((const float2*)&g_c[rd][hh[1]][bbj[1]][kk0]);
        }

        for (int i = tid; i < 72 * 32; i += NTHR) {
            int rr  = i >> 5;
            int kq  = (i & 31) << 2;
            int hhs = h_lo + cgid * 8 - 1 + (rr >> 3);
            int bb2 = bg * 8 + (rr & 7);
            float4 v = make_float4(0.f, 0.f, 0.f, 0.f);
            if (hhs >= 0 && hhs < Fc)
                v = __ldcg((const float4*)&g_h[rd][hhs][bb2][kq]);
            float* dst = s_h2 + rr * HSTRIDE + kq * 2;
            *(float2*)(dst)     = make_float2(v.x, v.x);
            *(float2*)(dst + 2) = make_float2(v.y, v.y);
            *(float2*)(dst + 4) = make_float2(v.z, v.z);
            *(float2*)(dst + 6) = make_float2(v.w, v.w);
        }
        __syncthreads();

#pragma unroll 2
        for (int k2 = 0; k2 < 64; k2++) {
            ulonglong2 wv[5];
#pragma unroll
            for (int g = 0; g < 5; g++)
                wv[g] = *(const ulonglong2*)(wp + ((g << 8) + 2 * k2) * 2);
            unsigned long long h0a = *(const unsigned long long*)(lf0 + 4 * k2);
            unsigned long long h0b = *(const unsigned long long*)(lf0 + 4 * k2 + 2);
            unsigned long long h1a = *(const unsigned long long*)(lf1 + 4 * k2);
            unsigned long long h1b = *(const unsigned long long*)(lf1 + 4 * k2 + 2);
#pragma unroll
            for (int g = 0; g < 5; g++) {
                acc[0][g] = fma2(wv[g].x, h0a, acc[0][g]);
                acc[1][g] = fma2(wv[g].x, h1a, acc[1][g]);
            }
#pragma unroll
            for (int g = 0; g < 5; g++) {
                acc[0][g] = fma2(wv[g].y, h0b, acc[0][g]);
                acc[1][g] = fma2(wv[g].y, h1b, acc[1][g]);
            }
        }
#pragma unroll 2
        for (int k2 = 0; k2 < 64; k2++) {
            ulonglong2 wv[5];
#pragma unroll
            for (int g = 0; g < 5; g++)
                wv[g] = *(const ulonglong2*)(wp + ((g << 8) + 128 + 2 * k2) * 2);
            unsigned long long h0a = *(const unsigned long long*)(up0 + 4 * k2);
            unsigned long long h0b = *(const unsigned long long*)(up0 + 4 * k2 + 2);
            unsigned long long h1a = *(const unsigned long long*)(up1 + 4 * k2);
            unsigned long long h1b = *(const unsigned long long*)(up1 + 4 * k2 + 2);
#pragma unroll
            for (int g = 0; g < 5; g++) {
                acc[0][g] = fma2(wv[g].x, h0a, acc[0][g]);
                acc[1][g] = fma2(wv[g].x, h1a, acc[1][g]);
            }
#pragma unroll
            for (int g = 0; g < 5; g++) {
                acc[0][g] = fma2(wv[g].y, h0b, acc[0][g]);
                acc[1][g] = fma2(wv[g].y, h1b, acc[1][g]);
            }
        }

#pragma unroll
        for (int j = 0; j < 2; j++) {
            if (!val[j]) continue;
            float zi0, zi1, zg0, zg1, za0, za1, zb0, zb1, zo0, zo1;
            unpack2f(acc[j][0], zi0, zi1);
            unpack2f(acc[j][1], zg0, zg1);
            unpack2f(acc[j][2], za0, za1);
            unpack2f(acc[j][3], zb0, zb1);
            unpack2f(acc[j][4], zo0, zo1);
            const int H = hh[j], W = ww[j], B = bbj[j];
            const int row = rowj[j];

            float2 cl, cu;
            if (!regB) {
                cl = c_reg[j];
                if (row >= 8)
                    cu = *(const float2*)&s_c[(((rd * 8 + cg) * 64) + row - 8) * 2];
                else
                    cu = (H > 0) ? cbnd : make_float2(0.f, 0.f);
            } else {
                cu = c_reg[j];
                if (row < 56)
                    cl = *(const float2*)&s_c[(((rd * 8 + cg) * 64) + row + 8) * 2];
                else
                    cl = cbnd;
            }

            float cA = fsig(za0) * cl.x + fsig(zb0) * cu.x + fsig(zi0) * ftanh(zg0);
            float cB = fsig(za1) * cl.y + fsig(zb1) * cu.y + fsig(zi1) * ftanh(zg1);
            float hA = fsig(zo0) * ftanh(cA);
            float hB = fsig(zo1) * ftanh(cB);

            c_reg[j] = make_float2(cA, cB);
            *(float2*)&s_c[(((wr * 8 + cg) * 64) + row) * 2] = make_float2(cA, cB);
            if (row < 8 || row >= 56)
                __stcg((float2*)&g_c[wr][H][B][kk0], make_float2(cA, cB));
            __stcg((float2*)&g_h[wr][H][B][kk0], make_float2(hA, hB));

            atomicAdd(&g_feat[B][W][kk0],     hA);
            atomicAdd(&g_feat[B][W][kk0 + 1], hB);
        }

        gbar_arrive(bg);
    }
}

// ---------------------------------------------------------------------------
// FC + log-softmax (validated R8/R12 version).
// ---------------------------------------------------------------------------
#define FCW 8
#define FC_SMEM ((HIDc*Vc + FCW*HIDc) * 4)
__global__ __launch_bounds__(128)
void fc_kernel(const float* __restrict__ W_fc, const float* __restrict__ b_fc)
{
    extern __shared__ float fsm[];
    float* s_wfc = fsm;
    float* s_f   = fsm + HIDc * Vc;

    const int wt = blockIdx.x, b = blockIdx.y, tid = threadIdx.x;
    const int wid = tid >> 5, lid = tid & 31;

    for (int i = tid; i < HIDc * Vc; i += 128) s_wfc[i] = W_fc[i];
    for (int i = tid; i < FCW * HIDc; i += 128)
        s_f[i] = g_feat[b][wt * FCW + (i >> 7)][i & 127];
    __syncthreads();

    for (int ws = 0; ws < 2; ws++) {
        const int wloc = wid * 2 + ws;
        const int w = wt * FCW + wloc;
        const float* f = s_f + wloc * HIDc;
        float lg[4];
#pragma unroll
        for (int i = 0; i < 4; i++) {
            int col = lid + 32 * i;
            float a = (col < Vc) ? b_fc[col] : NEGF;
            if (col < Vc) {
#pragma unroll 8
                for (int k = 0; k < HIDc; k++)
                    a = fmaf(f[k], s_wfc[k * Vc + col], a);
            }
            lg[i] = a;
        }
        float m = fmaxf(fmaxf(lg[0], lg[1]), fmaxf(lg[2], lg[3]));
#pragma unroll
        for (int o = 16; o > 0; o >>= 1)
            m = fmaxf(m, __shfl_xor_sync(0xffffffff, m, o));
        float s = 0.f;
#pragma unroll
        for (int i = 0; i < 4; i++) s += __expf(lg[i] - m);
#pragma unroll
        for (int o = 16; o > 0; o >>= 1)
            s += __shfl_xor_sync(0xffffffff, s, o);
        float lse = m + __logf(s);
#pragma unroll
        for (int i = 0; i < 4; i++) {
            int col = lid + 32 * i;
            if (col < Vc) g_logp[b][w][col] = lg[i] - lse;
        }
    }
}

// ---------------------------------------------------------------------------
// CTC alpha: 128 threads per batch. Phase 1: gather all needed logp values
// (32 label cols + blank col x 256 t) into smem with full MLP. Phase 2:
// warp 0 runs the alpha chain from smem (LDS hits, no L2 stalls).
// s_lp layout: [t][j], stride 33; j<32 = label j's logp, j=32 = blank's.
// ---------------------------------------------------------------------------
#define CTC_SMEM ((Tc * 33 + 36) * 4)
__global__ __launch_bounds__(128)
void ctc_kernel(const int* __restrict__ y, float* __restrict__ out)
{
    extern __shared__ float csm[];
    float* s_lp  = csm;                 // [256][33]
    int*   s_lbl = (int*)(csm + Tc * 33);  // [32]

    const int b = blockIdx.x, tid = threadIdx.x;
    const float* lp = &g_logp[b][0][0];

    if (tid < LBLc) s_lbl[tid] = y[b * LBLc + tid];
    __syncthreads();

    // Gather: 256*33 = 8448 scattered loads, MLP-limited not latency-limited.
    for (int i = tid; i < Tc * 33; i += 128) {
        int t = i / 33;
        int j = i - t * 33;
        int col = (j < 32) ? s_lbl[j] : (Vc - 1);
        s_lp[i] = __ldcg(&lp[t * Vc + col]);
    }
    __syncthreads();

    if (tid >= 32) return;
    const int l = tid;
    const int lbl = s_lbl[l];
    const int lblp = __shfl_up_sync(0xffffffffu, lbl, 1);
    const bool sk = (l > 0) && (lbl != lblp);

    float a0 = (l == 0) ? s_lp[32] : NEGF;      // t=0 blank
    float a1 = (l == 0) ? s_lp[0]  : NEGF;      // t=0 label0
    float a2 = NEGF;                             // lane31: state 64

    for (int t = 1; t < Tc; t++) {
        const float lpy = s_lp[t * 33 + l];
        const float lpb = s_lp[t * 33 + 32];

        float pa1 = __shfl_up_sync(0xffffffffu, a1, 1);
        if (l == 0) pa1 = NEGF;

        float m0 = fmaxf(a0, pa1);
        float n0 = m0 + __logf(__expf(a0 - m0) + __expf(pa1 - m0)) + lpb;

        float s2 = sk ? pa1 : NEGF;
        float m1 = fmaxf(a1, fmaxf(a0, s2));
        float n1 = m1 + __logf(__expf(a1 - m1) + __expf(a0 - m1) +
                               __expf(s2 - m1)) + lpy;

        float n2 = a2;
        if (l == 31) {
            float m2 = fmaxf(a2, a1);
            n2 = m2 + __logf(__expf(a2 - m2) + __expf(a1 - m2)) + lpb;
        }
        a0 = n0; a1 = n1; a2 = n2;
    }

    if (l == 31) {
        float m = fmaxf(a2, a1);
        out[b] = -(m + __logf(__expf(a2 - m) + __expf(a1 - m)));
    }
}

// ---------------------------------------------------------------------------
// Inputs: X, y, Wx, Wh1, Wh2, b, W_fc, b_fc. Output: float[32].
// ---------------------------------------------------------------------------
extern "C" void kernel_launch(void* const* d_in, const int* in_sizes, int n_in,
                              void* d_out, int out_size)
{
    const float* X    = (const float*)d_in[0];
    const int*   y    = (const int*)  d_in[1];
    const float* Wx   = (const float*)d_in[2];
    const float* Wh1  = (const float*)d_in[3];
    const float* Wh2  = (const float*)d_in[4];
    const float* bias = (const float*)d_in[5];
    const float* W_fc = (const float*)d_in[6];
    const float* b_fc = (const float*)d_in[7];
    float* out = (float*)d_out;

    cudaFuncSetAttribute(mdlstm_persist,
                         cudaFuncAttributeMaxDynamicSharedMemorySize, SMEM_BYTES);
    cudaFuncSetAttribute(fc_kernel,
                         cudaFuncAttributeMaxDynamicSharedMemorySize, FC_SMEM);
    cudaFuncSetAttribute(ctc_kernel,
                         cudaFuncAttributeMaxDynamicSharedMemorySize, CTC_SMEM);

    init_kernel<<<256, 256>>>();
    mdlstm_persist<<<NCTA, NTHR, SMEM_BYTES>>>(X, Wx, Wh1, Wh2, bias);
    fc_kernel<<<dim3(Tc / FCW, Bc), 128, FC_SMEM>>>(W_fc, b_fc);
    ctc_kernel<<<Bc, 128, CTC_SMEM>>>(y, out);
}

// round 16
// speedup vs baseline: 1.0220x; 1.0220x over previous
#include <cuda_runtime.h>
#include <math.h>

#define Bc   32
#define Tc   256
#define Fc   32
#define HIDc 128
#define ZW   640
#define Vc   101
#define LBLc 32
#define NEGF (-1e30f)

#define NCTA 128
#define NTHR 256
#define WSTR2 1282                  // per-kcol weight stride (floats): 5*128*2 + 2
#define HSTR2 130                   // per-row h stride (floats): 128 + 2
#define SCSTR 65                    // per-kcol c-exchange stride
#define SW2 (16*WSTR2)              // 20512
#define SH2 (72*HSTR2)              // 9360
#define SC2 (2*16*SCSTR)            // 2080
#define SMEM_BYTES ((SW2+SH2+SC2)*4)

// ---------------------------------------------------------------------------
// Device scratch.
// ---------------------------------------------------------------------------
__device__ __align__(16) float g_h[2][Fc][Bc][HIDc];
__device__ __align__(16) float g_c[2][Fc][Bc][HIDc];
__device__ __align__(16) float g_feat[Bc][Tc][HIDc];
__device__ __align__(16) float g_logp[Bc][Tc][Vc];
__device__ unsigned g_cnt4[4 * 32];
__device__ unsigned g_gen4[4 * 32];

__device__ __forceinline__ float fsig(float x) {
    return __fdividef(1.0f, 1.0f + __expf(-x));
}
__device__ __forceinline__ float ftanh(float x) {
    return 1.0f - __fdividef(2.0f, __expf(2.0f * x) + 1.0f);
}
__device__ __forceinline__ unsigned long long pack2f(float lo, float hi) {
    unsigned long long r;
    asm("mov.b64 %0, {%1, %2};" : "=l"(r) : "f"(lo), "f"(hi));
    return r;
}
__device__ __forceinline__ void unpack2f(unsigned long long v, float& lo, float& hi) {
    asm("mov.b64 {%0, %1}, %2;" : "=f"(lo), "=f"(hi) : "l"(v));
}
__device__ __forceinline__ unsigned long long fma2(unsigned long long a,
                                                   unsigned long long b,
                                                   unsigned long long c) {
    unsigned long long d;
    asm("fma.rn.f32x2 %0, %1, %2, %3;" : "=l"(d) : "l"(a), "l"(b), "l"(c));
    return d;
}

__global__ void init_kernel() {
    const int nh = 2 * Fc * Bc * HIDc;
    float* ph = &g_h[0][0][0][0];
    float* pc = &g_c[0][0][0][0];
    for (int i = blockIdx.x * blockDim.x + threadIdx.x; i < nh;
         i += gridDim.x * blockDim.x) { ph[i] = 0.0f; pc[i] = 0.0f; }
    const int nf = Bc * Tc * HIDc;
    float* pf = &g_feat[0][0][0];
    for (int i = blockIdx.x * blockDim.x + threadIdx.x; i < nf;
         i += gridDim.x * blockDim.x) pf[i] = 0.0f;
    if (blockIdx.x == 0 && threadIdx.x < 4 * 32) {
        g_cnt4[threadIdx.x] = 0u;
        g_gen4[threadIdx.x] = 0u;
    }
}

// Split per-bg grid barrier (32 CTAs).
__device__ __forceinline__ void gbar_arrive(int bg) {
    __syncthreads();
    if (threadIdx.x == 0) {
        unsigned old;
        asm volatile("atom.acq_rel.gpu.global.add.u32 %0, [%1], %2;"
                     : "=r"(old) : "l"(&g_cnt4[bg * 32]), "r"(1u) : "memory");
        unsigned done = old + 1u;
        if ((done & 31u) == 0u) {
            asm volatile("st.release.gpu.global.u32 [%0], %1;"
                         :: "l"(&g_gen4[bg * 32]), "r"(done >> 5) : "memory");
        }
    }
}
__device__ __forceinline__ void gbar_wait(unsigned target, int bg) {
    const unsigned* gen = &g_gen4[bg * 32];
    unsigned cur;
    do {
        asm volatile("ld.acquire.gpu.global.u32 %0, [%1];"
                     : "=r"(cur) : "l"(gen) : "memory");
    } while (cur < target);
}

// ---------------------------------------------------------------------------
// Persistent MDLSTM wavefront — k-pair FFMA2 layout.
// 128 CTAs = 8 jkb x 4 bg x 4 cgid, 256 threads.
// Thread (kcol = tid>>4, rgrp = tid&15) owns 1 k-col x 5 gates x 4 rows
// (rows rgrp+16j). acc pairs over (k even, k odd); z = lo + hi at the end.
// h in smem un-duplicated [row][k] stride 130 (conflict-free); weights as
// (w_2k, w_2k+1) u64 pairs per column.
// ---------------------------------------------------------------------------
__global__ __launch_bounds__(NTHR, 1)
void mdlstm_persist(const float* __restrict__ X,
                    const float* __restrict__ Wx,
                    const float* __restrict__ Wh1,
                    const float* __restrict__ Wh2,
                    const float* __restrict__ bias)
{
    extern __shared__ float smem[];
    float* s_w = smem;                  // [kcol][g*128+k2][2]
    float* s_h = smem + SW2;            // [rr 0..71][k 0..127]
    float* s_c = smem + SW2 + SH2;      // [p][kcol][row], stride 65

    const int tid  = threadIdx.x;
    const int bx   = blockIdx.x;
    const int jkb  = bx & 7;
    const int bg   = (bx >> 3) & 3;
    const int cgid = bx >> 5;

    const int kcol = tid >> 4;          // 0..15
    const int rgrp = tid & 15;          // 0..15

    // One-time: weights as k-pairs. k2<64 -> Wh1 rows 2k2+c; else Wh2.
    for (int i = tid; i < 16 * 5 * 128 * 2; i += NTHR) {
        int c   = i & 1;
        int t   = i >> 1;
        int k2  = t & 127;
        int t2  = t >> 7;
        int g   = t2 % 5;
        int kcl = t2 / 5;
        int col = g * HIDc + jkb * 16 + kcl;
        float v = (k2 < 64) ? Wh1[(2 * k2 + c) * ZW + col]
                            : Wh2[(2 * (k2 - 64) + c) * ZW + col];
        s_w[kcl * WSTR2 + ((g << 7) + k2) * 2 + c] = v;
    }

    const int kk = jkb * 16 + kcol;
    float wxs[5], bls[5];
#pragma unroll
    for (int g = 0; g < 5; g++) {
        wxs[g] = Wx[g * HIDc + kk];
        bls[g] = bias[g * HIDc + kk];
    }

    int rowj[4], cellj[4];
#pragma unroll
    for (int j = 0; j < 4; j++) {
        rowj[j]  = rgrp + 16 * j;
        cellj[j] = cgid * 8 + (rowj[j] >> 3);
    }
    const int bb = bg * 8 + (rgrp & 7);   // same batch for all 4 rows

    const float* wp = s_w + kcol * WSTR2;
    const float* upp[4];
    const float* lfp[4];
#pragma unroll
    for (int j = 0; j < 4; j++) {
        upp[j] = s_h + rowj[j] * HSTR2;
        lfp[j] = upp[j] + 8 * HSTR2;
    }

    float c_reg[4] = {0.f, 0.f, 0.f, 0.f};

    __syncthreads();

    for (int d = 0; d < Tc + Fc - 1; d++) {
        const int h_lo = (d > Tc - 1) ? d - (Tc - 1) : 0;
        const int h_hi = (d < Fc - 1) ? d : (Fc - 1);
        const int ncells = h_hi - h_lo + 1;
        const int rd = (d + 1) & 1, wr = d & 1;
        const bool regB = (d > Tc - 1);

        bool val[4]; int H[4], W[4];
#pragma unroll
        for (int j = 0; j < 4; j++) {
            val[j] = cellj[j] < ncells;
            H[j]   = h_lo + cellj[j];
            W[j]   = d - H[j];
        }

        // Peer-independent: X loads + z0 into acc.lo (before barrier wait).
        float xv[4];
#pragma unroll
        for (int j = 0; j < 4; j++)
            xv[j] = val[j] ? __ldg(&X[bb * (Tc * Fc) + W[j] * Fc + H[j]]) : 0.f;

        unsigned long long acc[4][5];
#pragma unroll
        for (int j = 0; j < 4; j++)
#pragma unroll
            for (int g = 0; g < 5; g++)
                acc[j][g] = pack2f(fmaf(xv[j], wxs[g], bls[g]), 0.0f);

        if (d > 0) gbar_wait((unsigned)d, bg);

        // Boundary c (cross-CTA cell neighbor), scalar.
        float cbnd = 0.f;
        if (!regB) {
            if (rgrp < 8 && val[0] && H[0] > 0)
                cbnd = __ldcg(&g_c[rd][H[0] - 1][bb][kk]);
        } else {
            if (rgrp >= 8 && val[3])
                cbnd = __ldcg(&g_c[rd][H[3]][bb][kk]);
        }

        // Stage 9 state rows x 8 batches, un-duplicated.
        for (int i = tid; i < 72 * 32; i += NTHR) {
            int rr  = i >> 5;
            int kq  = (i & 31) << 2;
            int hhs = h_lo + cgid * 8 - 1 + (rr >> 3);
            int bb2 = bg * 8 + (rr & 7);
            float4 v = make_float4(0.f, 0.f, 0.f, 0.f);
            if (hhs >= 0 && hhs < Fc)
                v = __ldcg((const float4*)&g_h[rd][hhs][bb2][kq]);
            float* dst = s_h + rr * HSTR2 + kq;
            *(float2*)(dst)     = make_float2(v.x, v.y);
            *(float2*)(dst + 2) = make_float2(v.z, v.w);
        }
        __syncthreads();

        // z += h_left @ Wh1 (k-pairs 0..63)
#pragma unroll 2
        for (int k2 = 0; k2 < 64; k2++) {
            unsigned long long wv[5];
#pragma unroll
            for (int g = 0; g < 5; g++)
                wv[g] = *(const unsigned long long*)(wp + ((g << 7) + k2) * 2);
            unsigned long long h0 = *(const unsigned long long*)(lfp[0] + 2 * k2);
            unsigned long long h1 = *(const unsigned long long*)(lfp[1] + 2 * k2);
            unsigned long long h2 = *(const unsigned long long*)(lfp[2] + 2 * k2);
            unsigned long long h3 = *(const unsigned long long*)(lfp[3] + 2 * k2);
#pragma unroll
            for (int g = 0; g < 5; g++) {
                acc[0][g] = fma2(wv[g], h0, acc[0][g]);
                acc[1][g] = fma2(wv[g], h1, acc[1][g]);
                acc[2][g] = fma2(wv[g], h2, acc[2][g]);
                acc[3][g] = fma2(wv[g], h3, acc[3][g]);
            }
        }
        // z += h_up @ Wh2 (k-pairs 64..127)
#pragma unroll 2
        for (int k2 = 0; k2 < 64; k2++) {
            unsigned long long wv[5];
#pragma unroll
            for (int g = 0; g < 5; g++)
                wv[g] = *(const unsigned long long*)(wp + ((g << 7) + 64 + k2) * 2);
            unsigned long long h0 = *(const unsigned long long*)(upp[0] + 2 * k2);
            unsigned long long h1 = *(const unsigned long long*)(upp[1] + 2 * k2);
            unsigned long long h2 = *(const unsigned long long*)(upp[2] + 2 * k2);
            unsigned long long h3 = *(const unsigned long long*)(upp[3] + 2 * k2);
#pragma unroll
            for (int g = 0; g < 5; g++) {
                acc[0][g] = fma2(wv[g], h0, acc[0][g]);
                acc[1][g] = fma2(wv[g], h1, acc[1][g]);
                acc[2][g] = fma2(wv[g], h2, acc[2][g]);
                acc[3][g] = fma2(wv[g], h3, acc[3][g]);
            }
        }

        // Gates (z order: i, g, f1, f2, o); z = lo + hi.
#pragma unroll
        for (int j = 0; j < 4; j++) {
            if (!val[j]) continue;
            float z[5];
#pragma unroll
            for (int g = 0; g < 5; g++) {
                float lo, hi;
                unpack2f(acc[j][g], lo, hi);
                z[g] = lo + hi;
            }
            const int row = rowj[j];

            float cl, cu;
            if (!regB) {
                cl = c_reg[j];
                cu = (row >= 8) ? s_c[(rd * 16 + kcol) * SCSTR + row - 8]
                                : ((H[j] > 0) ? cbnd : 0.f);
            } else {
                cu = c_reg[j];
                cl = (row < 56) ? s_c[(rd * 16 + kcol) * SCSTR + row + 8]
                                : cbnd;
            }

            float c = fsig(z[2]) * cl + fsig(z[3]) * cu + fsig(z[0]) * ftanh(z[1]);
            float h = fsig(z[4]) * ftanh(c);

            c_reg[j] = c;
            s_c[(wr * 16 + kcol) * SCSTR + row] = c;
            if (row < 8 || row >= 56)
                __stcg(&g_c[wr][H[j]][bb][kk], c);
            __stcg(&g_h[wr][H[j]][bb][kk], h);
            atomicAdd(&g_feat[bb][W[j]][kk], h);
        }

        gbar_arrive(bg);
    }
}

// ---------------------------------------------------------------------------
// FC + log-softmax (validated version).
// ---------------------------------------------------------------------------
#define FCW 8
#define FC_SMEM ((HIDc*Vc + FCW*HIDc) * 4)
__global__ __launch_bounds__(128)
void fc_kernel(const float* __restrict__ W_fc, const float* __restrict__ b_fc)
{
    extern __shared__ float fsm[];
    float* s_wfc = fsm;
    float* s_f   = fsm + HIDc * Vc;

    const int wt = blockIdx.x, b = blockIdx.y, tid = threadIdx.x;
    const int wid = tid >> 5, lid = tid & 31;

    for (int i = tid; i < HIDc * Vc; i += 128) s_wfc[i] = W_fc[i];
    for (int i = tid; i < FCW * HIDc; i += 128)
        s_f[i] = g_feat[b][wt * FCW + (i >> 7)][i & 127];
    __syncthreads();

    for (int ws = 0; ws < 2; ws++) {
        const int wloc = wid * 2 + ws;
        const int w = wt * FCW + wloc;
        const float* f = s_f + wloc * HIDc;
        float lg[4];
#pragma unroll
        for (int i = 0; i < 4; i++) {
            int col = lid + 32 * i;
            float a = (col < Vc) ? b_fc[col] : NEGF;
            if (col < Vc) {
#pragma unroll 8
                for (int k = 0; k < HIDc; k++)
                    a = fmaf(f[k], s_wfc[k * Vc + col], a);
            }
            lg[i] = a;
        }
        float m = fmaxf(fmaxf(lg[0], lg[1]), fmaxf(lg[2], lg[3]));
#pragma unroll
        for (int o = 16; o > 0; o >>= 1)
            m = fmaxf(m, __shfl_xor_sync(0xffffffff, m, o));
        float s = 0.f;
#pragma unroll
        for (int i = 0; i < 4; i++) s += __expf(lg[i] - m);
#pragma unroll
        for (int o = 16; o > 0; o >>= 1)
            s += __shfl_xor_sync(0xffffffff, s, o);
        float lse = m + __logf(s);
#pragma unroll
        for (int i = 0; i < 4; i++) {
            int col = lid + 32 * i;
            if (col < Vc) g_logp[b][w][col] = lg[i] - lse;
        }
    }
}

// ---------------------------------------------------------------------------
// CTC alpha (validated R15 smem-preload version).
// ---------------------------------------------------------------------------
#define CTC_SMEM ((Tc * 33 + 36) * 4)
__global__ __launch_bounds__(128)
void ctc_kernel(const int* __restrict__ y, float* __restrict__ out)
{
    extern __shared__ float csm[];
    float* s_lp  = csm;
    int*   s_lbl = (int*)(csm + Tc * 33);

    const int b = blockIdx.x, tid = threadIdx.x;
    const float* lp = &g_logp[b][0][0];

    if (tid < LBLc) s_lbl[tid] = y[b * LBLc + tid];
    __syncthreads();

    for (int i = tid; i < Tc * 33; i += 128) {
        int t = i / 33;
        int j = i - t * 33;
        int col = (j < 32) ? s_lbl[j] : (Vc - 1);
        s_lp[i] = __ldcg(&lp[t * Vc + col]);
    }
    __syncthreads();

    if (tid >= 32) return;
    const int l = tid;
    const int lbl = s_lbl[l];
    const int lblp = __shfl_up_sync(0xffffffffu, lbl, 1);
    const bool sk = (l > 0) && (lbl != lblp);

    float a0 = (l == 0) ? s_lp[32] : NEGF;
    float a1 = (l == 0) ? s_lp[0]  : NEGF;
    float a2 = NEGF;

    for (int t = 1; t < Tc; t++) {
        const float lpy = s_lp[t * 33 + l];
        const float lpb = s_lp[t * 33 + 32];

        float pa1 = __shfl_up_sync(0xffffffffu, a1, 1);
        if (l == 0) pa1 = NEGF;

        float m0 = fmaxf(a0, pa1);
        float n0 = m0 + __logf(__expf(a0 - m0) + __expf(pa1 - m0)) + lpb;

        float s2 = sk ? pa1 : NEGF;
        float m1 = fmaxf(a1, fmaxf(a0, s2));
        float n1 = m1 + __logf(__expf(a1 - m1) + __expf(a0 - m1) +
                               __expf(s2 - m1)) + lpy;

        float n2 = a2;
        if (l == 31) {
            float m2 = fmaxf(a2, a1);
            n2 = m2 + __logf(__expf(a2 - m2) + __expf(a1 - m2)) + lpb;
        }
        a0 = n0; a1 = n1; a2 = n2;
    }

    if (l == 31) {
        float m = fmaxf(a2, a1);
        out[b] = -(m + __logf(__expf(a2 - m) + __expf(a1 - m)));
    }
}

// ---------------------------------------------------------------------------
// Inputs: X, y, Wx, Wh1, Wh2, b, W_fc, b_fc. Output: float[32].
// ---------------------------------------------------------------------------
extern "C" void kernel_launch(void* const* d_in, const int* in_sizes, int n_in,
                              void* d_out, int out_size)
{
    const float* X    = (const float*)d_in[0];
    const int*   y    = (const int*)  d_in[1];
    const float* Wx   = (const float*)d_in[2];
    const float* Wh1  = (const float*)d_in[3];
    const float* Wh2  = (const float*)d_in[4];
    const float* bias = (const float*)d_in[5];
    const float* W_fc = (const float*)d_in[6];
    const float* b_fc = (const float*)d_in[7];
    float* out = (float*)d_out;

    cudaFuncSetAttribute(mdlstm_persist,
                         cudaFuncAttributeMaxDynamicSharedMemorySize, SMEM_BYTES);
    cudaFuncSetAttribute(fc_kernel,
                         cudaFuncAttributeMaxDynamicSharedMemorySize, FC_SMEM);
    cudaFuncSetAttribute(ctc_kernel,
                         cudaFuncAttributeMaxDynamicSharedMemorySize, CTC_SMEM);

    init_kernel<<<256, 256>>>();
    mdlstm_persist<<<NCTA, NTHR, SMEM_BYTES>>>(X, Wx, Wh1, Wh2, bias);
    fc_kernel<<<dim3(Tc / FCW, Bc), 128, FC_SMEM>>>(W_fc, b_fc);
    ctc_kernel<<<Bc, 128, CTC_SMEM>>>(y, out);
}